// round 3
// baseline (speedup 1.0000x reference)
#include <cuda_runtime.h>

// B_Splines fused: out[i][j] = spline(x[i]; coefs) * spline(t[j]; coefs_2)
// degree P=3, N_COEFS=128, knots[132] open-uniform on [0,1].
//
// Single DRAM-write-bound kernel. Each CTA owns a 128-row x 1024-col tile of
// the 8192x8192 fp32 output (512 CTAs total). Spline values are recomputed
// redundantly per CTA (4 nonzero basis fns per point, fast divides on the
// idle MUFU pipe); the bigger tile amortizes this prologue to ~4% of the
// per-CTA store drain.
//
// Inputs (metadata order): x[8192], t[8192], knots[132], coefs[128], coefs_2[128]
// Output: float32 [8192, 8192]

#define NX 8192
#define NT 8192
#define PDEG 3

#define TPB 256
#define ROWS_PER_BLOCK 128
#define COLS_PER_BLOCK (TPB * 4)   // 1024

// Cubic B-spline evaluation at one point: knot-span find (uniform interior
// knots give the initial guess; local search against the actual fp32 knot
// array fixes linspace rounding), then the triangular basis algorithm
// (NURBS book A2.2) over the 4 nonzero basis functions.
__device__ __forceinline__ float spline_eval(float xv,
                                             const float* __restrict__ knots,
                                             const float* __restrict__ c) {
    int k = 3 + (int)floorf(xv * 125.0f);
    k = max(3, min(127, k));
    while (k > 3   && xv <  __ldg(knots + k))     k--;
    while (k < 127 && xv >= __ldg(knots + k + 1)) k++;

    float left[PDEG + 1], right[PDEG + 1], N[PDEG + 1];
    N[0] = 1.0f;
#pragma unroll
    for (int j = 1; j <= PDEG; j++) {
        left[j]  = xv - __ldg(knots + (k + 1 - j));
        right[j] = __ldg(knots + (k + j)) - xv;
        float saved = 0.0f;
#pragma unroll
        for (int r = 0; r < j; r++) {
            float temp = __fdividef(N[r], right[r + 1] + left[j - r]);
            N[r] = saved + right[r + 1] * temp;
            saved = left[j - r] * temp;
        }
        N[j] = saved;
    }

    float s = 0.0f;
#pragma unroll
    for (int r = 0; r <= PDEG; r++)
        s += __ldg(c + (k - 3 + r)) * N[r];
    return s;
}

__global__ __launch_bounds__(TPB) void bspline_outer_fused(
    const float* __restrict__ x,
    const float* __restrict__ t,
    const float* __restrict__ knots,
    const float* __restrict__ coefs,
    const float* __restrict__ coefs2,
    float* __restrict__ out) {
    __shared__ float s_sx[ROWS_PER_BLOCK];

    const int tid = threadIdx.x;
    const int j   = blockIdx.x * COLS_PER_BLOCK + tid * 4;  // base column
    const int r0  = blockIdx.y * ROWS_PER_BLOCK;            // base row

    // Row spline values -> SMEM (threads 0..127), overlapped with column evals.
    if (tid < ROWS_PER_BLOCK) {
        float xv = __ldg(x + r0 + tid);
        s_sx[tid] = spline_eval(xv, knots, coefs);
    }

    // Column spline values for this thread's 4 columns (independent -> ILP).
    float4 tv = *reinterpret_cast<const float4*>(t + j);
    float4 s4;
    s4.x = spline_eval(tv.x, knots, coefs2);
    s4.y = spline_eval(tv.y, knots, coefs2);
    s4.z = spline_eval(tv.z, knots, coefs2);
    s4.w = spline_eval(tv.w, knots, coefs2);

    __syncthreads();

    // Store drain: 128 rows x 16B per thread, fully coalesced.
    float4* outp = reinterpret_cast<float4*>(out + (size_t)r0 * NT + j);
#pragma unroll 8
    for (int r = 0; r < ROWS_PER_BLOCK; r++) {
        float a = s_sx[r];
        float4 o;
        o.x = a * s4.x;
        o.y = a * s4.y;
        o.z = a * s4.z;
        o.w = a * s4.w;
        *outp = o;
        outp += NT / 4;
    }
}

extern "C" void kernel_launch(void* const* d_in, const int* in_sizes, int n_in,
                              void* d_out, int out_size) {
    const float* x      = (const float*)d_in[0];
    const float* t      = (const float*)d_in[1];
    const float* knots  = (const float*)d_in[2];
    const float* coefs  = (const float*)d_in[3];
    const float* coefs2 = (const float*)d_in[4];
    float* out = (float*)d_out;

    dim3 grid(NT / COLS_PER_BLOCK, NX / ROWS_PER_BLOCK);  // (8, 64)
    bspline_outer_fused<<<grid, TPB>>>(x, t, knots, coefs, coefs2, out);
}

// round 4
// speedup vs baseline: 1.0628x; 1.0628x over previous
#include <cuda_runtime.h>

// B_Splines fused: out[i][j] = spline(x[i]; coefs) * spline(t[j]; coefs_2)
// degree P=3, N_COEFS=128, knots[132] open-uniform on [0,1], h = 1/125.
//
// Single DRAM-write-bound kernel, 64-row x 1024-col tiles, grid = 1024 CTAs
// (all resident in one wave at 8 CTAs/SM -> max store concurrency, the
// measured-best drain shape). The per-CTA redundant spline prologue is made
// division-free: open-uniform knots mean every Cox-de Boor denominator is
// exactly n*h, n in {1,2,3}, derived with integer clamps -> constant-select
// reciprocal. Zero MUFU traffic; numerators still read the actual fp32 knot
// array for span/indicator parity with the reference.
//
// Inputs (metadata order): x[8192], t[8192], knots[132], coefs[128], coefs_2[128]
// Output: float32 [8192, 8192]

#define NX 8192
#define NT 8192

#define TPB 256
#define ROWS_PER_BLOCK 64
#define COLS_PER_BLOCK (TPB * 4)   // 1024

__device__ __forceinline__ int clampi(int i) {
    return min(max(i, 3), 128);
}

// reciprocal of (n * h) for n in {1,2,3}, h = 1/125
__device__ __forceinline__ float recip_n(int n) {
    return n == 1 ? 125.0f : (n == 2 ? 62.5f : 41.666668f);
}

// denominator reciprocal for knots[k+a] - knots[k+b] (open-uniform closed form)
__device__ __forceinline__ float rden(int k, int a, int b) {
    return recip_n(clampi(k + a) - clampi(k + b));
}

__device__ __forceinline__ float spline_eval(float xv,
                                             const float* __restrict__ knots,
                                             const float* __restrict__ c) {
    // Knot span: uniform interior gives the guess; local fix against actual
    // fp32 knots keeps indicator parity (t[k] <= x < t[k+1]).
    int k = 3 + (int)floorf(xv * 125.0f);
    k = max(3, min(127, k));
    while (k > 3   && xv <  __ldg(knots + k))     k--;
    while (k < 127 && xv >= __ldg(knots + k + 1)) k++;

    // Local knots (all L1-hit; 528 B array).
    float tm2 = __ldg(knots + k - 2);
    float tm1 = __ldg(knots + k - 1);
    float t0  = __ldg(knots + k);
    float t1  = __ldg(knots + k + 1);
    float t2  = __ldg(knots + k + 2);
    float t3  = __ldg(knots + k + 3);

    float l1 = xv - t0,  r1 = t1 - xv;
    float l2 = xv - tm1, r2 = t2 - xv;
    float l3 = xv - tm2, r3 = t3 - xv;

    // Triangular algorithm (NURBS A2.2) with closed-form denominators.
    float N0, N1, N2, N3, temp, saved;
    // j = 1
    temp = rden(k, 1, 0);                 // 1/(t1 - t0)
    N1 = l1 * temp;
    N0 = r1 * temp;
    // j = 2
    temp  = N0 * rden(k, 1, -1);          // /(t1 - tm1)
    N0    = r1 * temp;
    saved = l2 * temp;
    temp  = N1 * rden(k, 2, 0);           // /(t2 - t0)
    N1    = saved + r2 * temp;
    N2    = l1 * temp;
    // j = 3
    temp  = N0 * rden(k, 1, -2);          // /(t1 - tm2)
    N0    = r1 * temp;
    saved = l3 * temp;
    temp  = N1 * rden(k, 2, -1);          // /(t2 - tm1)
    N1    = saved + r2 * temp;
    saved = l2 * temp;
    temp  = N2 * rden(k, 3, 0);           // /(t3 - t0)
    N2    = saved + r3 * temp;
    N3    = l1 * temp;

    return __ldg(c + k - 3) * N0 + __ldg(c + k - 2) * N1 +
           __ldg(c + k - 1) * N2 + __ldg(c + k)     * N3;
}

__global__ __launch_bounds__(TPB) void bspline_outer_fused(
    const float* __restrict__ x,
    const float* __restrict__ t,
    const float* __restrict__ knots,
    const float* __restrict__ coefs,
    const float* __restrict__ coefs2,
    float* __restrict__ out) {
    __shared__ float s_sx[ROWS_PER_BLOCK];

    const int tid = threadIdx.x;
    const int j   = blockIdx.x * COLS_PER_BLOCK + tid * 4;  // base column
    const int r0  = blockIdx.y * ROWS_PER_BLOCK;            // base row

    // Row spline values -> SMEM (threads 0..63).
    if (tid < ROWS_PER_BLOCK) {
        float xv = __ldg(x + r0 + tid);
        s_sx[tid] = spline_eval(xv, knots, coefs);
    }

    // Column spline values for this thread's 4 columns (independent -> ILP).
    float4 tv = *reinterpret_cast<const float4*>(t + j);
    float4 s4;
    s4.x = spline_eval(tv.x, knots, coefs2);
    s4.y = spline_eval(tv.y, knots, coefs2);
    s4.z = spline_eval(tv.z, knots, coefs2);
    s4.w = spline_eval(tv.w, knots, coefs2);

    __syncthreads();

    // Store drain: 64 rows x 16B per thread, fully coalesced, default stores.
    float4* outp = reinterpret_cast<float4*>(out + (size_t)r0 * NT + j);
#pragma unroll 8
    for (int r = 0; r < ROWS_PER_BLOCK; r++) {
        float a = s_sx[r];
        float4 o;
        o.x = a * s4.x;
        o.y = a * s4.y;
        o.z = a * s4.z;
        o.w = a * s4.w;
        *outp = o;
        outp += NT / 4;
    }
}

extern "C" void kernel_launch(void* const* d_in, const int* in_sizes, int n_in,
                              void* d_out, int out_size) {
    const float* x      = (const float*)d_in[0];
    const float* t      = (const float*)d_in[1];
    const float* knots  = (const float*)d_in[2];
    const float* coefs  = (const float*)d_in[3];
    const float* coefs2 = (const float*)d_in[4];
    float* out = (float*)d_out;

    dim3 grid(NT / COLS_PER_BLOCK, NX / ROWS_PER_BLOCK);  // (8, 128)
    bspline_outer_fused<<<grid, TPB>>>(x, t, knots, coefs, coefs2, out);
}